// round 2
// baseline (speedup 1.0000x reference)
#include <cuda_runtime.h>
#include <cuda_bf16.h>
#include <cstdint>

// ---------------------------------------------------------------------------
// Problem dims
// ---------------------------------------------------------------------------
#define B_   32
#define N_   2048
#define F_   1024
#define HS_  8192
#define HF_  4096
#define M1_  (B_ * F_)   // 32768 rows (b,f) for sorted-MLP GEMMs
#define M2_  (B_ * N_)   // 65536 rows (b,n) for feature-MLP GEMMs
#define OUT_ 1024

// ---------------------------------------------------------------------------
// Device-global scratch (allocation-free rule: __device__ arrays)
// ---------------------------------------------------------------------------
constexpr size_t SZ_XS  = (size_t)M1_ * N_;    // 67.1M
constexpr size_t SZ_H   = (size_t)M1_ * HS_;   // 268.4M
constexpr size_t SZ_Y2  = (size_t)M2_ * F_;    // 67.1M
constexpr size_t SZ_H2  = (size_t)M2_ * HF_;   // 268.4M
constexpr size_t SZ_SW1 = (size_t)HS_ * N_;
constexpr size_t SZ_SW2 = (size_t)N_ * HS_;
constexpr size_t SZ_FW1 = (size_t)HF_ * F_;
constexpr size_t SZ_FW2 = (size_t)OUT_ * HF_;

__device__ __nv_bfloat16 g_xs_hi[SZ_XS];
__device__ __nv_bfloat16 g_xs_lo[SZ_XS];
__device__ unsigned short g_invp[SZ_XS];
__device__ __nv_bfloat16 g_h_hi[SZ_H];
__device__ __nv_bfloat16 g_h_lo[SZ_H];
__device__ __nv_bfloat16 g_y2_hi[SZ_Y2];
__device__ __nv_bfloat16 g_y2_lo[SZ_Y2];
__device__ __nv_bfloat16 g_h2_hi[SZ_H2];
__device__ __nv_bfloat16 g_h2_lo[SZ_H2];
__device__ __nv_bfloat16 g_sw1_hi[SZ_SW1];
__device__ __nv_bfloat16 g_sw1_lo[SZ_SW1];
__device__ __nv_bfloat16 g_sw2_hi[SZ_SW2];
__device__ __nv_bfloat16 g_sw2_lo[SZ_SW2];
__device__ __nv_bfloat16 g_fw1_hi[SZ_FW1];
__device__ __nv_bfloat16 g_fw1_lo[SZ_FW1];
__device__ __nv_bfloat16 g_fw2_hi[SZ_FW2];
__device__ __nv_bfloat16 g_fw2_lo[SZ_FW2];

// ---------------------------------------------------------------------------
// Small helpers
// ---------------------------------------------------------------------------
__device__ __forceinline__ void split_val(float v, __nv_bfloat16& h, __nv_bfloat16& l) {
    h = __float2bfloat16(v);
    l = __float2bfloat16(v - __bfloat162float(h));
}

__global__ void split_kernel(const float* __restrict__ in,
                             __nv_bfloat16* __restrict__ hi,
                             __nv_bfloat16* __restrict__ lo, int n) {
    int i = blockIdx.x * 256 + threadIdx.x;
    if (i < n) {
        __nv_bfloat16 h, l;
        split_val(in[i], h, l);
        hi[i] = h; lo[i] = l;
    }
}

// ---------------------------------------------------------------------------
// Sort kernel: one block per (b,f) row. Stable argsort via (ordered_u32, idx)
// packed u64 keys + bitonic sort. Produces xs (scatter x[j] -> xs[p[j]]) split
// into bf16 hi/lo, and invp[i] = rank(i) (for the final unsort-scatter).
// ---------------------------------------------------------------------------
__global__ __launch_bounds__(512) void sort_kernel(
    const float* __restrict__ x,
    __nv_bfloat16* __restrict__ xs_hi, __nv_bfloat16* __restrict__ xs_lo,
    unsigned short* __restrict__ invp)
{
    __shared__ unsigned long long keys[N_];
    __shared__ float xorig[N_];
    __shared__ float xsv[N_];
    __shared__ unsigned short invs[N_];

    const int m = blockIdx.x;          // m = b*F + f
    const int b = m >> 10;             // /F_
    const int f = m & (F_ - 1);
    const float* xrow = x + ((size_t)b * N_) * F_ + f;   // x[b, j, f], stride F_

    for (int j = threadIdx.x; j < N_; j += 512) {
        float v = xrow[(size_t)j * F_];
        unsigned u = __float_as_uint(v);
        u = (u & 0x80000000u) ? ~u : (u | 0x80000000u);   // order-preserving map
        keys[j] = ((unsigned long long)u << 16) | (unsigned)j;
        xorig[j] = v;
    }
    __syncthreads();

    // bitonic sort ascending
    for (int k = 2; k <= N_; k <<= 1) {
        for (int j = k >> 1; j > 0; j >>= 1) {
            for (int t = threadIdx.x; t < N_ / 2; t += 512) {
                int i = ((t & ~(j - 1)) << 1) | (t & (j - 1));
                int l = i | j;
                bool up = ((i & k) == 0);
                unsigned long long a = keys[i], c = keys[l];
                if ((a > c) == up) { keys[i] = c; keys[l] = a; }
            }
            __syncthreads();
        }
    }

    // sorted slot jslot holds p[jslot]. scatter: xs[p[j]] = x[j]; inv[p[j]] = j
    for (int jslot = threadIdx.x; jslot < N_; jslot += 512) {
        int pj = (int)(keys[jslot] & 0xFFFFu);
        xsv[pj] = xorig[jslot];
        invs[pj] = (unsigned short)jslot;
    }
    __syncthreads();

    size_t base = (size_t)m * N_;
    for (int i = threadIdx.x; i < N_; i += 512) {
        __nv_bfloat16 h, l;
        split_val(xsv[i], h, l);
        xs_hi[base + i] = h;
        xs_lo[base + i] = l;
        invp[base + i] = invs[i];
    }
}

// ---------------------------------------------------------------------------
// GEMM: C[M,N] = A[M,K] @ B[N,K]^T using bf16 split-3 (hi*hi + hi*lo + lo*hi)
// 128x128 block tile, BK=32, 2-stage cp.async, 8 warps (2x4), warp tile 64x32.
// EPI: 0 = bias+relu -> split bf16 out
//      1 = bias+skip(xs)+unsort-scatter -> split bf16 out (Y2 layout [B,N,F])
//      3 = bias -> fp32 out
// ---------------------------------------------------------------------------
__device__ __forceinline__ void cp16(unsigned s, const void* g) {
    asm volatile("cp.async.cg.shared.global [%0], [%1], 16;\n" :: "r"(s), "l"(g) : "memory");
}
__device__ __forceinline__ void cp_commit() {
    asm volatile("cp.async.commit_group;\n" ::: "memory");
}
__device__ __forceinline__ void cp_wait0() {
    asm volatile("cp.async.wait_group 0;\n" ::: "memory");
}
__device__ __forceinline__ void ldsm4(unsigned* r, unsigned addr) {
    asm volatile("ldmatrix.sync.aligned.m8n8.x4.shared.b16 {%0,%1,%2,%3}, [%4];\n"
        : "=r"(r[0]), "=r"(r[1]), "=r"(r[2]), "=r"(r[3]) : "r"(addr));
}
__device__ __forceinline__ void ldsm2(unsigned* r, unsigned addr) {
    asm volatile("ldmatrix.sync.aligned.m8n8.x2.shared.b16 {%0,%1}, [%2];\n"
        : "=r"(r[0]), "=r"(r[1]) : "r"(addr));
}
__device__ __forceinline__ void mma_bf16(float* c, const unsigned* a, const unsigned* b) {
    asm volatile(
        "mma.sync.aligned.m16n8k16.row.col.f32.bf16.bf16.f32 "
        "{%0,%1,%2,%3}, {%4,%5,%6,%7}, {%8,%9}, {%0,%1,%2,%3};\n"
        : "+f"(c[0]), "+f"(c[1]), "+f"(c[2]), "+f"(c[3])
        : "r"(a[0]), "r"(a[1]), "r"(a[2]), "r"(a[3]), "r"(b[0]), "r"(b[1]));
}

// smem layout (bytes, per stage = 40960): [Ah 10240][Al 10240][Bh 10240][Bl 10240]
// each tile array: 128 rows * (32 + 8 pad) bf16 = 80 B/row (conflict-free ldmatrix)
#define SMEM_BYTES 81920

__device__ __forceinline__ void stage_load(
    unsigned sst,   // sbase + stage*40960
    const __nv_bfloat16* __restrict__ Ah, const __nv_bfloat16* __restrict__ Al,
    const __nv_bfloat16* __restrict__ Bh, const __nv_bfloat16* __restrict__ Bl,
    int m0, int n0, int K, int k0, int tid)
{
#pragma unroll
    for (int it = 0; it < 2; it++) {
        int c = tid + it * 256;          // 512 chunks of 16B per array
        int row = c >> 2, cc = c & 3;
        unsigned so = sst + row * 80 + cc * 16;
        size_t ga = (size_t)(m0 + row) * K + k0 + cc * 8;
        size_t gb = (size_t)(n0 + row) * K + k0 + cc * 8;
        cp16(so,          Ah + ga);
        cp16(so + 10240,  Al + ga);
        cp16(so + 20480,  Bh + gb);
        cp16(so + 30720,  Bl + gb);
    }
    cp_commit();
}

template <int EPI>
__global__ __launch_bounds__(256, 1) void gemm_kernel(
    int M, int N, int K,
    const __nv_bfloat16* __restrict__ Ah, const __nv_bfloat16* __restrict__ Al,
    const __nv_bfloat16* __restrict__ Bh, const __nv_bfloat16* __restrict__ Bl,
    const float* __restrict__ bias,
    __nv_bfloat16* __restrict__ Oh, __nv_bfloat16* __restrict__ Ol,
    float* __restrict__ Of,
    const __nv_bfloat16* __restrict__ Sh, const __nv_bfloat16* __restrict__ Sl,
    const unsigned short* __restrict__ invp)
{
    extern __shared__ __nv_bfloat16 smem[];
    const int tid = threadIdx.x;
    const int m0 = blockIdx.y * 128;
    const int n0 = blockIdx.x * 128;
    const unsigned sbase = (unsigned)__cvta_generic_to_shared(smem);

    float acc[4][4][4];
#pragma unroll
    for (int a = 0; a < 4; a++)
#pragma unroll
        for (int b = 0; b < 4; b++)
#pragma unroll
            for (int e = 0; e < 4; e++) acc[a][b][e] = 0.f;

    const int nk = K >> 5;
    const int lane = tid & 31;
    const int wid = tid >> 5;
    const int wm = wid >> 2;   // 0..1  -> 64 rows
    const int wn = wid & 3;    // 0..3  -> 32 cols

    stage_load(sbase, Ah, Al, Bh, Bl, m0, n0, K, 0, tid);

    for (int kt = 0; kt < nk; kt++) {
        cp_wait0();
        __syncthreads();
        if (kt + 1 < nk)
            stage_load(sbase + ((kt + 1) & 1) * 40960, Ah, Al, Bh, Bl, m0, n0, K,
                       (kt + 1) << 5, tid);

        const unsigned sst = sbase + (kt & 1) * 40960;
#pragma unroll
        for (int step = 0; step < 2; step++) {
            unsigned a_h[4][4], a_l[4][4], b_h[4][2], b_l[4][2];
            const int arow = lane & 15;
            const int acol = step * 16 + ((lane >> 4) << 3);
#pragma unroll
            for (int mt = 0; mt < 4; mt++) {
                unsigned ad = sst + (wm * 64 + mt * 16 + arow) * 80 + acol * 2;
                ldsm4(a_h[mt], ad);
                ldsm4(a_l[mt], ad + 10240);
            }
            const int brow = lane & 7;
            const int bcol = step * 16 + (((lane >> 3) & 1) << 3);
#pragma unroll
            for (int nt = 0; nt < 4; nt++) {
                unsigned bd = sst + 20480 + (wn * 32 + nt * 8 + brow) * 80 + bcol * 2;
                ldsm2(b_h[nt], bd);
                ldsm2(b_l[nt], bd + 10240);
            }
#pragma unroll
            for (int mt = 0; mt < 4; mt++)
#pragma unroll
                for (int nt = 0; nt < 4; nt++) {
                    mma_bf16(acc[mt][nt], a_h[mt], b_h[nt]);
                    mma_bf16(acc[mt][nt], a_h[mt], b_l[nt]);
                    mma_bf16(acc[mt][nt], a_l[mt], b_h[nt]);
                }
        }
        __syncthreads();   // before next iter's stage_load overwrites this buffer
    }

    // ---------------- epilogue ----------------
    const int quad = lane >> 2;
    const int qt = (lane & 3) << 1;
#pragma unroll
    for (int mt = 0; mt < 4; mt++) {
#pragma unroll
        for (int nt = 0; nt < 4; nt++) {
#pragma unroll
            for (int e = 0; e < 4; e++) {
                int m = m0 + wm * 64 + mt * 16 + quad + ((e >> 1) << 3);
                int n = n0 + wn * 32 + nt * 8 + qt + (e & 1);
                float v = acc[mt][nt][e] + bias[n];
                if (EPI == 0) {
                    v = fmaxf(v, 0.f);
                    size_t o = (size_t)m * N + n;
                    __nv_bfloat16 h, l; split_val(v, h, l);
                    Oh[o] = h; Ol[o] = l;
                } else if (EPI == 1) {
                    size_t si = (size_t)m * N + n;
                    v += __bfloat162float(Sh[si]) + __bfloat162float(Sl[si]);
                    int bb = m >> 10;              // m = b*F + f
                    int f  = m & (F_ - 1);
                    int np = invp[si];             // final position of element n
                    size_t o = ((size_t)(bb * N_ + np)) * F_ + f;  // Y2[b, np, f]
                    __nv_bfloat16 h, l; split_val(v, h, l);
                    Oh[o] = h; Ol[o] = l;
                } else {  // EPI == 3
                    Of[(size_t)m * N + n] = v;
                }
            }
        }
    }
}

// ---------------------------------------------------------------------------
// Launch
// ---------------------------------------------------------------------------
extern "C" void kernel_launch(void* const* d_in, const int* in_sizes, int n_in,
                              void* d_out, int out_size) {
    const float* x   = (const float*)d_in[0];
    const float* sw1 = (const float*)d_in[1];
    const float* sb1 = (const float*)d_in[2];
    const float* sw2 = (const float*)d_in[3];
    const float* sb2 = (const float*)d_in[4];
    const float* fw1 = (const float*)d_in[5];
    const float* fb1 = (const float*)d_in[6];
    const float* fw2 = (const float*)d_in[7];
    const float* fb2 = (const float*)d_in[8];
    float* out = (float*)d_out;

    void *p_xs_hi, *p_xs_lo, *p_invp, *p_h_hi, *p_h_lo, *p_y2_hi, *p_y2_lo,
         *p_h2_hi, *p_h2_lo, *p_sw1h, *p_sw1l, *p_sw2h, *p_sw2l,
         *p_fw1h, *p_fw1l, *p_fw2h, *p_fw2l;
    cudaGetSymbolAddress(&p_xs_hi, g_xs_hi);
    cudaGetSymbolAddress(&p_xs_lo, g_xs_lo);
    cudaGetSymbolAddress(&p_invp,  g_invp);
    cudaGetSymbolAddress(&p_h_hi,  g_h_hi);
    cudaGetSymbolAddress(&p_h_lo,  g_h_lo);
    cudaGetSymbolAddress(&p_y2_hi, g_y2_hi);
    cudaGetSymbolAddress(&p_y2_lo, g_y2_lo);
    cudaGetSymbolAddress(&p_h2_hi, g_h2_hi);
    cudaGetSymbolAddress(&p_h2_lo, g_h2_lo);
    cudaGetSymbolAddress(&p_sw1h,  g_sw1_hi);
    cudaGetSymbolAddress(&p_sw1l,  g_sw1_lo);
    cudaGetSymbolAddress(&p_sw2h,  g_sw2_hi);
    cudaGetSymbolAddress(&p_sw2l,  g_sw2_lo);
    cudaGetSymbolAddress(&p_fw1h,  g_fw1_hi);
    cudaGetSymbolAddress(&p_fw1l,  g_fw1_lo);
    cudaGetSymbolAddress(&p_fw2h,  g_fw2_hi);
    cudaGetSymbolAddress(&p_fw2l,  g_fw2_lo);

    cudaFuncSetAttribute(gemm_kernel<0>, cudaFuncAttributeMaxDynamicSharedMemorySize, SMEM_BYTES);
    cudaFuncSetAttribute(gemm_kernel<1>, cudaFuncAttributeMaxDynamicSharedMemorySize, SMEM_BYTES);
    cudaFuncSetAttribute(gemm_kernel<3>, cudaFuncAttributeMaxDynamicSharedMemorySize, SMEM_BYTES);

    // weight splits (fp32 -> bf16 hi/lo)
    split_kernel<<<(int)((SZ_SW1 + 255) / 256), 256>>>(sw1, (__nv_bfloat16*)p_sw1h, (__nv_bfloat16*)p_sw1l, (int)SZ_SW1);
    split_kernel<<<(int)((SZ_SW2 + 255) / 256), 256>>>(sw2, (__nv_bfloat16*)p_sw2h, (__nv_bfloat16*)p_sw2l, (int)SZ_SW2);
    split_kernel<<<(int)((SZ_FW1 + 255) / 256), 256>>>(fw1, (__nv_bfloat16*)p_fw1h, (__nv_bfloat16*)p_fw1l, (int)SZ_FW1);
    split_kernel<<<(int)((SZ_FW2 + 255) / 256), 256>>>(fw2, (__nv_bfloat16*)p_fw2h, (__nv_bfloat16*)p_fw2l, (int)SZ_FW2);

    // sort + xs + inverse permutation
    sort_kernel<<<M1_, 512>>>(x, (__nv_bfloat16*)p_xs_hi, (__nv_bfloat16*)p_xs_lo,
                              (unsigned short*)p_invp);

    // G1: H = relu(Xs @ sw1^T + sb1)        [32768, 8192]
    {
        dim3 g(HS_ / 128, M1_ / 128);
        gemm_kernel<0><<<g, 256, SMEM_BYTES>>>(
            M1_, HS_, N_,
            (__nv_bfloat16*)p_xs_hi, (__nv_bfloat16*)p_xs_lo,
            (__nv_bfloat16*)p_sw1h, (__nv_bfloat16*)p_sw1l, sb1,
            (__nv_bfloat16*)p_h_hi, (__nv_bfloat16*)p_h_lo, nullptr,
            nullptr, nullptr, nullptr);
    }
    // G2: Y = H @ sw2^T + sb2 + Xs, then unsort+transpose-scatter into Y2[B,N,F]
    {
        dim3 g(N_ / 128, M1_ / 128);
        gemm_kernel<1><<<g, 256, SMEM_BYTES>>>(
            M1_, N_, HS_,
            (__nv_bfloat16*)p_h_hi, (__nv_bfloat16*)p_h_lo,
            (__nv_bfloat16*)p_sw2h, (__nv_bfloat16*)p_sw2l, sb2,
            (__nv_bfloat16*)p_y2_hi, (__nv_bfloat16*)p_y2_lo, nullptr,
            (__nv_bfloat16*)p_xs_hi, (__nv_bfloat16*)p_xs_lo,
            (const unsigned short*)p_invp);
    }
    // G3: H2 = relu(Y2 @ fw1^T + fb1)       [65536, 4096]
    {
        dim3 g(HF_ / 128, M2_ / 128);
        gemm_kernel<0><<<g, 256, SMEM_BYTES>>>(
            M2_, HF_, F_,
            (__nv_bfloat16*)p_y2_hi, (__nv_bfloat16*)p_y2_lo,
            (__nv_bfloat16*)p_fw1h, (__nv_bfloat16*)p_fw1l, fb1,
            (__nv_bfloat16*)p_h2_hi, (__nv_bfloat16*)p_h2_lo, nullptr,
            nullptr, nullptr, nullptr);
    }
    // G4: out = H2 @ fw2^T + fb2            [65536, 1024] fp32
    {
        dim3 g(OUT_ / 128, M2_ / 128);
        gemm_kernel<3><<<g, 256, SMEM_BYTES>>>(
            M2_, OUT_, HF_,
            (__nv_bfloat16*)p_h2_hi, (__nv_bfloat16*)p_h2_lo,
            (__nv_bfloat16*)p_fw2h, (__nv_bfloat16*)p_fw2l, fb2,
            nullptr, nullptr, out,
            nullptr, nullptr, nullptr);
    }
}

// round 8
// speedup vs baseline: 1.2329x; 1.2329x over previous
#include <cuda_runtime.h>
#include <cuda_bf16.h>
#include <cstdint>

// ---------------------------------------------------------------------------
// Problem dims
// ---------------------------------------------------------------------------
#define B_   32
#define N_   2048
#define F_   1024
#define HS_  8192
#define HF_  4096
#define M1_  (B_ * F_)   // 32768
#define M2_  (B_ * N_)   // 65536
#define OUT_ 1024

// ---------------------------------------------------------------------------
// Device-global scratch
// ---------------------------------------------------------------------------
constexpr size_t SZ_XS  = (size_t)M1_ * N_;
constexpr size_t SZ_H   = (size_t)M1_ * HS_;
constexpr size_t SZ_Y2  = (size_t)M2_ * F_;
constexpr size_t SZ_H2  = (size_t)M2_ * HF_;
constexpr size_t SZ_SW1 = (size_t)HS_ * N_;
constexpr size_t SZ_SW2 = (size_t)N_ * HS_;
constexpr size_t SZ_FW1 = (size_t)HF_ * F_;
constexpr size_t SZ_FW2 = (size_t)OUT_ * HF_;

__device__ __nv_bfloat16 g_xs_hi[SZ_XS];
__device__ __nv_bfloat16 g_xs_lo[SZ_XS];
__device__ unsigned short g_invp[SZ_XS];
__device__ __nv_bfloat16 g_h_hi[SZ_H];
__device__ __nv_bfloat16 g_h_lo[SZ_H];
__device__ __nv_bfloat16 g_y2_hi[SZ_Y2];
__device__ __nv_bfloat16 g_y2_lo[SZ_Y2];
__device__ __nv_bfloat16 g_h2_hi[SZ_H2];
__device__ __nv_bfloat16 g_h2_lo[SZ_H2];
__device__ __nv_bfloat16 g_sw1_hi[SZ_SW1];
__device__ __nv_bfloat16 g_sw1_lo[SZ_SW1];
__device__ __nv_bfloat16 g_sw2_hi[SZ_SW2];
__device__ __nv_bfloat16 g_sw2_lo[SZ_SW2];
__device__ __nv_bfloat16 g_fw1_hi[SZ_FW1];
__device__ __nv_bfloat16 g_fw1_lo[SZ_FW1];
__device__ __nv_bfloat16 g_fw2_hi[SZ_FW2];
__device__ __nv_bfloat16 g_fw2_lo[SZ_FW2];

// ---------------------------------------------------------------------------
// Helpers
// ---------------------------------------------------------------------------
__device__ __forceinline__ void split_val(float v, __nv_bfloat16& h, __nv_bfloat16& l) {
    h = __float2bfloat16(v);
    l = __float2bfloat16(v - __bfloat162float(h));
}

__global__ __launch_bounds__(256) void split_kernel(const float* __restrict__ in,
                             __nv_bfloat16* __restrict__ hi,
                             __nv_bfloat16* __restrict__ lo, int n) {
    int i = blockIdx.x * 256 + threadIdx.x;
    if (i < n) {
        __nv_bfloat16 h, l;
        split_val(in[i], h, l);
        hi[i] = h; lo[i] = l;
    }
}

// ---------------------------------------------------------------------------
// Sort kernel (validated R2)
// ---------------------------------------------------------------------------
__global__ __launch_bounds__(512) void sort_kernel(
    const float* __restrict__ x,
    __nv_bfloat16* __restrict__ xs_hi, __nv_bfloat16* __restrict__ xs_lo,
    unsigned short* __restrict__ invp)
{
    __shared__ unsigned long long keys[N_];
    __shared__ float xorig[N_];
    __shared__ float xsv[N_];
    __shared__ unsigned short invs[N_];

    const int m = blockIdx.x;
    const int b = m >> 10;
    const int f = m & (F_ - 1);
    const float* xrow = x + ((size_t)b * N_) * F_ + f;

    for (int j = threadIdx.x; j < N_; j += 512) {
        float v = xrow[(size_t)j * F_];
        unsigned u = __float_as_uint(v);
        u = (u & 0x80000000u) ? ~u : (u | 0x80000000u);
        keys[j] = ((unsigned long long)u << 16) | (unsigned)j;
        xorig[j] = v;
    }
    __syncthreads();

    for (int k = 2; k <= N_; k <<= 1) {
        for (int j = k >> 1; j > 0; j >>= 1) {
            for (int t = threadIdx.x; t < N_ / 2; t += 512) {
                int i = ((t & ~(j - 1)) << 1) | (t & (j - 1));
                int l = i | j;
                bool up = ((i & k) == 0);
                unsigned long long a = keys[i], c = keys[l];
                if ((a > c) == up) { keys[i] = c; keys[l] = a; }
            }
            __syncthreads();
        }
    }

    for (int jslot = threadIdx.x; jslot < N_; jslot += 512) {
        int pj = (int)(keys[jslot] & 0xFFFFu);
        xsv[pj] = xorig[jslot];
        invs[pj] = (unsigned short)jslot;
    }
    __syncthreads();

    size_t base = (size_t)m * N_;
    for (int i = threadIdx.x; i < N_; i += 512) {
        __nv_bfloat16 h, l;
        split_val(xsv[i], h, l);
        xs_hi[base + i] = h;
        xs_lo[base + i] = l;
        invp[base + i] = invs[i];
    }
}

// ---------------------------------------------------------------------------
// GEMM: C[M,N] = A[M,K] @ B[N,K]^T, bf16 split-3 (hh + hl + lh), mma.sync.
// 128x128 tile, BK=32, 3-stage cp.async, swizzled 64B rows, 2 CTAs/SM.
// ---------------------------------------------------------------------------
__device__ __forceinline__ void cp16(unsigned s, const void* g) {
    asm volatile("cp.async.cg.shared.global [%0], [%1], 16;\n" :: "r"(s), "l"(g) : "memory");
}
__device__ __forceinline__ void cp_commit() {
    asm volatile("cp.async.commit_group;\n" ::: "memory");
}
template <int Np>
__device__ __forceinline__ void cp_waitg() {
    asm volatile("cp.async.wait_group %0;\n" :: "n"(Np) : "memory");
}
__device__ __forceinline__ void ldsm4(unsigned* r, unsigned addr) {
    asm volatile("ldmatrix.sync.aligned.m8n8.x4.shared.b16 {%0,%1,%2,%3}, [%4];\n"
        : "=r"(r[0]), "=r"(r[1]), "=r"(r[2]), "=r"(r[3]) : "r"(addr));
}
__device__ __forceinline__ void ldsm2(unsigned* r, unsigned addr) {
    asm volatile("ldmatrix.sync.aligned.m8n8.x2.shared.b16 {%0,%1}, [%2];\n"
        : "=r"(r[0]), "=r"(r[1]) : "r"(addr));
}
__device__ __forceinline__ void mma_bf16(float* c, const unsigned* a, const unsigned* b) {
    asm volatile(
        "mma.sync.aligned.m16n8k16.row.col.f32.bf16.bf16.f32 "
        "{%0,%1,%2,%3}, {%4,%5,%6,%7}, {%8,%9}, {%0,%1,%2,%3};\n"
        : "+f"(c[0]), "+f"(c[1]), "+f"(c[2]), "+f"(c[3])
        : "r"(a[0]), "r"(a[1]), "r"(a[2]), "r"(a[3]), "r"(b[0]), "r"(b[1]));
}

// stage layout: 4 arrays x 128 rows x 64B, XOR-swizzled 16B chunks
#define SS_      32768
#define A_H_OFF  0
#define A_L_OFF  8192
#define B_H_OFF  16384
#define B_L_OFF  24576
#define SMEM_BYTES (3 * SS_)   // 98304

__device__ __forceinline__ unsigned sw_off(int row, int clog) {
    return (unsigned)(row * 64 + ((clog ^ (row & 3)) << 4));
}

__device__ __forceinline__ void stage_load(
    unsigned sst,
    const __nv_bfloat16* __restrict__ Ah, const __nv_bfloat16* __restrict__ Al,
    const __nv_bfloat16* __restrict__ Bh, const __nv_bfloat16* __restrict__ Bl,
    int m0, int n0, int K, int k0, int tid)
{
#pragma unroll
    for (int it = 0; it < 8; it++) {       // 2048 chunks / 256 threads
        int c = tid + it * 256;
        int arr = c >> 9;                  // 0:Ah 1:Al 2:Bh 3:Bl (uniform per it-pair)
        int cc = c & 511;
        int row = cc >> 2, clog = cc & 3;
        unsigned dst = sst + arr * 8192 + sw_off(row, clog);
        const __nv_bfloat16* base = (arr == 0) ? Ah : (arr == 1) ? Al : (arr == 2) ? Bh : Bl;
        int r0 = (arr < 2) ? m0 : n0;
        cp16(dst, base + (size_t)(r0 + row) * K + k0 + clog * 8);
    }
}

// EPI: 0 = bias+relu -> split bf16; 1 = bias+skip+unsort-scatter -> split bf16;
//      3 = bias -> fp32
template <int EPI>
__global__ __launch_bounds__(256, 2) void gemm_kernel(
    int M, int Nn, int K,
    const __nv_bfloat16* __restrict__ Ah, const __nv_bfloat16* __restrict__ Al,
    const __nv_bfloat16* __restrict__ Bh, const __nv_bfloat16* __restrict__ Bl,
    const float* __restrict__ bias,
    __nv_bfloat16* __restrict__ Oh, __nv_bfloat16* __restrict__ Ol,
    float* __restrict__ Of,
    const __nv_bfloat16* __restrict__ Sh, const __nv_bfloat16* __restrict__ Sl,
    const unsigned short* __restrict__ invp)
{
    extern __shared__ __nv_bfloat16 smem[];
    const int tid = threadIdx.x;
    const int m0 = blockIdx.y * 128;
    const int n0 = blockIdx.x * 128;
    const unsigned sbase = (unsigned)__cvta_generic_to_shared(smem);

    float acc[4][4][4];
#pragma unroll
    for (int a = 0; a < 4; a++)
#pragma unroll
        for (int b = 0; b < 4; b++)
#pragma unroll
            for (int e = 0; e < 4; e++) acc[a][b][e] = 0.f;

    const int nk = K >> 5;
    const int lane = tid & 31;
    const int wid = tid >> 5;
    const int wm = wid >> 2;   // 0..1 -> 64 rows
    const int wn = wid & 3;    // 0..3 -> 32 cols

    // prologue: 3 stages in flight
    stage_load(sbase + 0 * SS_, Ah, Al, Bh, Bl, m0, n0, K, 0, tid);      cp_commit();
    stage_load(sbase + 1 * SS_, Ah, Al, Bh, Bl, m0, n0, K, 32, tid);     cp_commit();
    stage_load(sbase + 2 * SS_, Ah, Al, Bh, Bl, m0, n0, K, 64, tid);     cp_commit();

    int sidx = 0;
    for (int kt = 0; kt < nk; kt++) {
        cp_waitg<2>();          // stage kt complete (this thread's part)
        __syncthreads();        // publish to all threads

        const unsigned sst = sbase + sidx * SS_;
#pragma unroll
        for (int step = 0; step < 2; step++) {
            unsigned a_h[4][4], a_l[4][4];
            const int arow = lane & 15;
            const int ag = step * 2 + (lane >> 4);
#pragma unroll
            for (int mt = 0; mt < 4; mt++) {
                int row = wm * 64 + mt * 16 + arow;
                unsigned off = sw_off(row, ag);
                ldsm4(a_h[mt], sst + A_H_OFF + off);
                ldsm4(a_l[mt], sst + A_L_OFF + off);
            }
            const int brow = wn * 32 + (lane & 7);
            const int bg = step * 2 + ((lane >> 3) & 1);
#pragma unroll
            for (int nt = 0; nt < 4; nt++) {
                int row = brow + nt * 8;
                unsigned off = sw_off(row, bg);
                unsigned b_h[2], b_l[2];
                ldsm2(b_h, sst + B_H_OFF + off);
                ldsm2(b_l, sst + B_L_OFF + off);
#pragma unroll
                for (int mt = 0; mt < 4; mt++) {
                    mma_bf16(acc[mt][nt], a_h[mt], b_h);
                    mma_bf16(acc[mt][nt], a_h[mt], b_l);
                    mma_bf16(acc[mt][nt], a_l[mt], b_h);
                }
            }
        }
        __syncthreads();        // all reads of stage sidx done

        if (kt + 3 < nk)
            stage_load(sbase + sidx * SS_, Ah, Al, Bh, Bl, m0, n0, K, (kt + 3) * 32, tid);
        cp_commit();            // keep group count consistent every iter
        sidx = (sidx == 2) ? 0 : sidx + 1;
    }

    // ---------------- epilogue (R2-validated semantics) ----------------
    const int quad = lane >> 2;
    const int qt = (lane & 3) << 1;
#pragma unroll
    for (int mt = 0; mt < 4; mt++) {
#pragma unroll
        for (int nt = 0; nt < 4; nt++) {
#pragma unroll
            for (int eh = 0; eh < 2; eh++) {     // row-half: e pairs (0,1) and (2,3)
                int m = m0 + wm * 64 + mt * 16 + quad + eh * 8;
                int n = n0 + wn * 32 + nt * 8 + qt;
                float v0 = acc[mt][nt][eh * 2 + 0] + bias[n];
                float v1 = acc[mt][nt][eh * 2 + 1] + bias[n + 1];
                if (EPI == 0) {
                    v0 = fmaxf(v0, 0.f); v1 = fmaxf(v1, 0.f);
                    size_t o = (size_t)m * Nn + n;
                    __nv_bfloat16 h0, l0, h1, l1;
                    split_val(v0, h0, l0); split_val(v1, h1, l1);
                    *(__nv_bfloat162*)(Oh + o) = __nv_bfloat162(h0, h1);
                    *(__nv_bfloat162*)(Ol + o) = __nv_bfloat162(l0, l1);
                } else if (EPI == 1) {
#pragma unroll
                    for (int e = 0; e < 2; e++) {
                        float v = (e == 0) ? v0 : v1;
                        int nn = n + e;
                        size_t si = (size_t)m * Nn + nn;
                        v += __bfloat162float(Sh[si]) + __bfloat162float(Sl[si]);
                        int bb = m >> 10;            // m = b*F + f
                        int f  = m & (F_ - 1);
                        int np = invp[si];
                        size_t o = ((size_t)(bb * N_ + np)) * F_ + f;
                        __nv_bfloat16 h, l; split_val(v, h, l);
                        Oh[o] = h; Ol[o] = l;
                    }
                } else {  // EPI == 3
                    *(float2*)(Of + (size_t)m * Nn + n) = make_float2(v0, v1);
                }
            }
        }
    }
}

// ---------------------------------------------------------------------------
// Launch
// ---------------------------------------------------------------------------
extern "C" void kernel_launch(void* const* d_in, const int* in_sizes, int n_in,
                              void* d_out, int out_size) {
    const float* x   = (const float*)d_in[0];
    const float* sw1 = (const float*)d_in[1];
    const float* sb1 = (const float*)d_in[2];
    const float* sw2 = (const float*)d_in[3];
    const float* sb2 = (const float*)d_in[4];
    const float* fw1 = (const float*)d_in[5];
    const float* fb1 = (const float*)d_in[6];
    const float* fw2 = (const float*)d_in[7];
    const float* fb2 = (const float*)d_in[8];
    float* out = (float*)d_out;

    void *p_xs_hi, *p_xs_lo, *p_invp, *p_h_hi, *p_h_lo, *p_y2_hi, *p_y2_lo,
         *p_h2_hi, *p_h2_lo, *p_sw1h, *p_sw1l, *p_sw2h, *p_sw2l,
         *p_fw1h, *p_fw1l, *p_fw2h, *p_fw2l;
    cudaGetSymbolAddress(&p_xs_hi, g_xs_hi);
    cudaGetSymbolAddress(&p_xs_lo, g_xs_lo);
    cudaGetSymbolAddress(&p_invp,  g_invp);
    cudaGetSymbolAddress(&p_h_hi,  g_h_hi);
    cudaGetSymbolAddress(&p_h_lo,  g_h_lo);
    cudaGetSymbolAddress(&p_y2_hi, g_y2_hi);
    cudaGetSymbolAddress(&p_y2_lo, g_y2_lo);
    cudaGetSymbolAddress(&p_h2_hi, g_h2_hi);
    cudaGetSymbolAddress(&p_h2_lo, g_h2_lo);
    cudaGetSymbolAddress(&p_sw1h,  g_sw1_hi);
    cudaGetSymbolAddress(&p_sw1l,  g_sw1_lo);
    cudaGetSymbolAddress(&p_sw2h,  g_sw2_hi);
    cudaGetSymbolAddress(&p_sw2l,  g_sw2_lo);
    cudaGetSymbolAddress(&p_fw1h,  g_fw1_hi);
    cudaGetSymbolAddress(&p_fw1l,  g_fw1_lo);
    cudaGetSymbolAddress(&p_fw2h,  g_fw2_hi);
    cudaGetSymbolAddress(&p_fw2l,  g_fw2_lo);

    cudaFuncSetAttribute(gemm_kernel<0>, cudaFuncAttributeMaxDynamicSharedMemorySize, SMEM_BYTES);
    cudaFuncSetAttribute(gemm_kernel<1>, cudaFuncAttributeMaxDynamicSharedMemorySize, SMEM_BYTES);
    cudaFuncSetAttribute(gemm_kernel<3>, cudaFuncAttributeMaxDynamicSharedMemorySize, SMEM_BYTES);

    split_kernel<<<(int)((SZ_SW1 + 255) / 256), 256>>>(sw1, (__nv_bfloat16*)p_sw1h, (__nv_bfloat16*)p_sw1l, (int)SZ_SW1);
    split_kernel<<<(int)((SZ_SW2 + 255) / 256), 256>>>(sw2, (__nv_bfloat16*)p_sw2h, (__nv_bfloat16*)p_sw2l, (int)SZ_SW2);
    split_kernel<<<(int)((SZ_FW1 + 255) / 256), 256>>>(fw1, (__nv_bfloat16*)p_fw1h, (__nv_bfloat16*)p_fw1l, (int)SZ_FW1);
    split_kernel<<<(int)((SZ_FW2 + 255) / 256), 256>>>(fw2, (__nv_bfloat16*)p_fw2h, (__nv_bfloat16*)p_fw2l, (int)SZ_FW2);

    sort_kernel<<<M1_, 512>>>(x, (__nv_bfloat16*)p_xs_hi, (__nv_bfloat16*)p_xs_lo,
                              (unsigned short*)p_invp);

    // G1: H = relu(Xs @ sw1^T + sb1)   [M1, HS]
    {
        dim3 g(HS_ / 128, M1_ / 128);
        gemm_kernel<0><<<g, 256, SMEM_BYTES>>>(
            M1_, HS_, N_,
            (__nv_bfloat16*)p_xs_hi, (__nv_bfloat16*)p_xs_lo,
            (__nv_bfloat16*)p_sw1h, (__nv_bfloat16*)p_sw1l, sb1,
            (__nv_bfloat16*)p_h_hi, (__nv_bfloat16*)p_h_lo, nullptr,
            nullptr, nullptr, nullptr);
    }
    // G2: Y = H @ sw2^T + sb2 + Xs, unsort+transpose-scatter into Y2[B,N,F]
    {
        dim3 g(N_ / 128, M1_ / 128);
        gemm_kernel<1><<<g, 256, SMEM_BYTES>>>(
            M1_, N_, HS_,
            (__nv_bfloat16*)p_h_hi, (__nv_bfloat16*)p_h_lo,
            (__nv_bfloat16*)p_sw2h, (__nv_bfloat16*)p_sw2l, sb2,
            (__nv_bfloat16*)p_y2_hi, (__nv_bfloat16*)p_y2_lo, nullptr,
            (__nv_bfloat16*)p_xs_hi, (__nv_bfloat16*)p_xs_lo,
            (const unsigned short*)p_invp);
    }
    // G3: H2 = relu(Y2 @ fw1^T + fb1)  [M2, HF]
    {
        dim3 g(HF_ / 128, M2_ / 128);
        gemm_kernel<0><<<g, 256, SMEM_BYTES>>>(
            M2_, HF_, F_,
            (__nv_bfloat16*)p_y2_hi, (__nv_bfloat16*)p_y2_lo,
            (__nv_bfloat16*)p_fw1h, (__nv_bfloat16*)p_fw1l, fb1,
            (__nv_bfloat16*)p_h2_hi, (__nv_bfloat16*)p_h2_lo, nullptr,
            nullptr, nullptr, nullptr);
    }
    // G4: out = H2 @ fw2^T + fb2       [M2, OUT] fp32
    {
        dim3 g(OUT_ / 128, M2_ / 128);
        gemm_kernel<3><<<g, 256, SMEM_BYTES>>>(
            M2_, OUT_, HF_,
            (__nv_bfloat16*)p_h2_hi, (__nv_bfloat16*)p_h2_lo,
            (__nv_bfloat16*)p_fw2h, (__nv_bfloat16*)p_fw2l, fb2,
            nullptr, nullptr, out,
            nullptr, nullptr, nullptr);
    }
}

// round 12
// speedup vs baseline: 1.5892x; 1.2890x over previous
#include <cuda_runtime.h>
#include <cuda_fp16.h>
#include <cstdint>

// ---------------------------------------------------------------------------
// Problem dims
// ---------------------------------------------------------------------------
#define B_   32
#define N_   2048
#define F_   1024
#define HS_  8192
#define HF_  4096
#define M1_  (B_ * F_)   // 32768
#define M2_  (B_ * N_)   // 65536
#define OUT_ 1024

// ---------------------------------------------------------------------------
// Device-global scratch
// ---------------------------------------------------------------------------
constexpr size_t SZ_XS  = (size_t)M1_ * N_;
constexpr size_t SZ_H   = (size_t)M1_ * HS_;
constexpr size_t SZ_Y2  = (size_t)M2_ * F_;
constexpr size_t SZ_H2  = (size_t)M2_ * HF_;
constexpr size_t SZ_SW1 = (size_t)HS_ * N_;
constexpr size_t SZ_SW2 = (size_t)N_ * HS_;
constexpr size_t SZ_FW1 = (size_t)HF_ * F_;
constexpr size_t SZ_FW2 = (size_t)OUT_ * HF_;

__device__ __half g_xs_hi[SZ_XS];
__device__ __half g_xs_lo[SZ_XS];
__device__ unsigned short g_invp[SZ_XS];
__device__ __half g_h_hi[SZ_H];
__device__ __half g_h_lo[SZ_H];
__device__ __half g_y2_hi[SZ_Y2];
__device__ __half g_y2_lo[SZ_Y2];
__device__ __half g_h2_hi[SZ_H2];
__device__ __half g_h2_lo[SZ_H2];
__device__ __half g_sw1[SZ_SW1];
__device__ __half g_sw2[SZ_SW2];
__device__ __half g_fw1[SZ_FW1];
__device__ __half g_fw2[SZ_FW2];

// ---------------------------------------------------------------------------
// Helpers
// ---------------------------------------------------------------------------
__device__ __forceinline__ void split_h(float v, __half& h, __half& l) {
    h = __float2half_rn(v);
    l = __float2half_rn(v - __half2float(h));
}

// round weights fp32 -> single fp16
__global__ __launch_bounds__(256) void round_kernel(const float* __restrict__ in,
                             __half* __restrict__ w, int n) {
    int i = blockIdx.x * 256 + threadIdx.x;
    if (i < n) w[i] = __float2half_rn(in[i]);
}

// ---------------------------------------------------------------------------
// Sort kernel (validated; outputs fp16 hi/lo pair)
// ---------------------------------------------------------------------------
__global__ __launch_bounds__(512) void sort_kernel(
    const float* __restrict__ x,
    __half* __restrict__ xs_hi, __half* __restrict__ xs_lo,
    unsigned short* __restrict__ invp)
{
    __shared__ unsigned long long keys[N_];
    __shared__ float xorig[N_];
    __shared__ float xsv[N_];
    __shared__ unsigned short invs[N_];

    const int m = blockIdx.x;
    const int b = m >> 10;
    const int f = m & (F_ - 1);
    const float* xrow = x + ((size_t)b * N_) * F_ + f;

    for (int j = threadIdx.x; j < N_; j += 512) {
        float v = xrow[(size_t)j * F_];
        unsigned u = __float_as_uint(v);
        u = (u & 0x80000000u) ? ~u : (u | 0x80000000u);
        keys[j] = ((unsigned long long)u << 16) | (unsigned)j;
        xorig[j] = v;
    }
    __syncthreads();

    for (int k = 2; k <= N_; k <<= 1) {
        for (int j = k >> 1; j > 0; j >>= 1) {
            for (int t = threadIdx.x; t < N_ / 2; t += 512) {
                int i = ((t & ~(j - 1)) << 1) | (t & (j - 1));
                int l = i | j;
                bool up = ((i & k) == 0);
                unsigned long long a = keys[i], c = keys[l];
                if ((a > c) == up) { keys[i] = c; keys[l] = a; }
            }
            __syncthreads();
        }
    }

    for (int jslot = threadIdx.x; jslot < N_; jslot += 512) {
        int pj = (int)(keys[jslot] & 0xFFFFu);
        xsv[pj] = xorig[jslot];
        invs[pj] = (unsigned short)jslot;
    }
    __syncthreads();

    size_t base = (size_t)m * N_;
    for (int i = threadIdx.x; i < N_; i += 512) {
        __half h, l;
        split_h(xsv[i], h, l);
        xs_hi[base + i] = h;
        xs_lo[base + i] = l;
        invp[base + i] = invs[i];
    }
}

// ---------------------------------------------------------------------------
// GEMM: C[M,N] = A[M,K] @ W[N,K]^T.  A = fp16 split-2 (Ah+Al), W = single fp16.
// C = Ah*W + Al*W  (2 mmas/tile).  128x128 tile, BK=32, 4-stage cp.async,
// swizzled 64B rows, 2 CTAs/SM, 1 barrier per K-tile.
// ---------------------------------------------------------------------------
__device__ __forceinline__ void cp16(unsigned s, const void* g) {
    asm volatile("cp.async.cg.shared.global [%0], [%1], 16;\n" :: "r"(s), "l"(g) : "memory");
}
__device__ __forceinline__ void cp_commit() {
    asm volatile("cp.async.commit_group;\n" ::: "memory");
}
template <int Np>
__device__ __forceinline__ void cp_waitg() {
    asm volatile("cp.async.wait_group %0;\n" :: "n"(Np) : "memory");
}
__device__ __forceinline__ void ldsm4(unsigned* r, unsigned addr) {
    asm volatile("ldmatrix.sync.aligned.m8n8.x4.shared.b16 {%0,%1,%2,%3}, [%4];\n"
        : "=r"(r[0]), "=r"(r[1]), "=r"(r[2]), "=r"(r[3]) : "r"(addr));
}
__device__ __forceinline__ void ldsm2(unsigned* r, unsigned addr) {
    asm volatile("ldmatrix.sync.aligned.m8n8.x2.shared.b16 {%0,%1}, [%2];\n"
        : "=r"(r[0]), "=r"(r[1]) : "r"(addr));
}
__device__ __forceinline__ void mma_f16(float* c, const unsigned* a, const unsigned* b) {
    asm volatile(
        "mma.sync.aligned.m16n8k16.row.col.f32.f16.f16.f32 "
        "{%0,%1,%2,%3}, {%4,%5,%6,%7}, {%8,%9}, {%0,%1,%2,%3};\n"
        : "+f"(c[0]), "+f"(c[1]), "+f"(c[2]), "+f"(c[3])
        : "r"(a[0]), "r"(a[1]), "r"(a[2]), "r"(a[3]), "r"(b[0]), "r"(b[1]));
}

// stage: Ah 8KB | Al 8KB | W 8KB, rows of 64B, XOR-swizzled 16B chunks
#define SS_      24576
#define A_H_OFF  0
#define A_L_OFF  8192
#define B_W_OFF  16384
#define NSTAGE   4
#define SMEM_BYTES (NSTAGE * SS_)   // 98304

__device__ __forceinline__ unsigned sw_off(int row, int clog) {
    return (unsigned)(row * 64 + ((clog ^ (row & 3)) << 4));
}

__device__ __forceinline__ void stage_load(
    unsigned sst,
    const __half* __restrict__ Ah, const __half* __restrict__ Al,
    const __half* __restrict__ Bw,
    int m0, int n0, int K, int k0, int tid)
{
#pragma unroll
    for (int it = 0; it < 6; it++) {       // 1536 chunks / 256 threads
        int c = tid + it * 256;
        int arr = c >> 9;                  // 0:Ah 1:Al 2:W
        int cc = c & 511;
        int row = cc >> 2, clog = cc & 3;
        unsigned dst = sst + arr * 8192 + sw_off(row, clog);
        const __half* base = (arr == 0) ? Ah : (arr == 1) ? Al : Bw;
        int r0 = (arr < 2) ? m0 : n0;
        cp16(dst, base + (size_t)(r0 + row) * K + k0 + clog * 8);
    }
}

// EPI: 0 = bias+relu -> fp16 pair; 1 = bias+skip+unsort-scatter -> fp16 pair;
//      3 = bias -> fp32
template <int EPI>
__global__ __launch_bounds__(256, 2) void gemm_kernel(
    int M, int Nn, int K,
    const __half* __restrict__ Ah, const __half* __restrict__ Al,
    const __half* __restrict__ Bw,
    const float* __restrict__ bias,
    __half* __restrict__ Oh, __half* __restrict__ Ol,
    float* __restrict__ Of,
    const __half* __restrict__ Sh, const __half* __restrict__ Sl,
    const unsigned short* __restrict__ invp)
{
    extern __shared__ __half smem[];
    const int tid = threadIdx.x;
    const int m0 = blockIdx.y * 128;
    const int n0 = blockIdx.x * 128;
    const unsigned sbase = (unsigned)__cvta_generic_to_shared(smem);

    float acc[4][4][4];
#pragma unroll
    for (int a = 0; a < 4; a++)
#pragma unroll
        for (int b = 0; b < 4; b++)
#pragma unroll
            for (int e = 0; e < 4; e++) acc[a][b][e] = 0.f;

    const int nk = K >> 5;
    const int lane = tid & 31;
    const int wid = tid >> 5;
    const int wm = wid >> 2;   // 0..1 -> 64 rows
    const int wn = wid & 3;    // 0..3 -> 32 cols

    // prologue: 3 stages in flight (4 buffers)
    stage_load(sbase + 0 * SS_, Ah, Al, Bw, m0, n0, K, 0, tid);   cp_commit();
    stage_load(sbase + 1 * SS_, Ah, Al, Bw, m0, n0, K, 32, tid);  cp_commit();
    stage_load(sbase + 2 * SS_, Ah, Al, Bw, m0, n0, K, 64, tid);  cp_commit();

    for (int kt = 0; kt < nk; kt++) {
        cp_waitg<2>();          // stage kt landed (this thread's chunks)
        __syncthreads();        // publish; also fences reuse of buffer (kt+3)%4

        const unsigned sst = sbase + (kt & (NSTAGE - 1)) * SS_;
#pragma unroll
        for (int step = 0; step < 2; step++) {
            unsigned a_h[4][4], a_l[4][4];
            const int arow = lane & 15;
            const int ag = step * 2 + (lane >> 4);
#pragma unroll
            for (int mt = 0; mt < 4; mt++) {
                int row = wm * 64 + mt * 16 + arow;
                unsigned off = sw_off(row, ag);
                ldsm4(a_h[mt], sst + A_H_OFF + off);
                ldsm4(a_l[mt], sst + A_L_OFF + off);
            }
            const int brow = wn * 32 + (lane & 7);
            const int bg = step * 2 + ((lane >> 3) & 1);
#pragma unroll
            for (int nt = 0; nt < 4; nt++) {
                int row = brow + nt * 8;
                unsigned off = sw_off(row, bg);
                unsigned bw[2];
                ldsm2(bw, sst + B_W_OFF + off);
                // limb-major: 4 independent mmas between same-acc reuses
#pragma unroll
                for (int mt = 0; mt < 4; mt++) mma_f16(acc[mt][nt], a_h[mt], bw);
#pragma unroll
                for (int mt = 0; mt < 4; mt++) mma_f16(acc[mt][nt], a_l[mt], bw);
            }
        }

        if (kt + 3 < nk)
            stage_load(sbase + ((kt + 3) & (NSTAGE - 1)) * SS_, Ah, Al, Bw,
                       m0, n0, K, (kt + 3) * 32, tid);
        cp_commit();            // keep group count uniform
    }

    // ---------------- epilogue ----------------
    const int quad = lane >> 2;
    const int qt = (lane & 3) << 1;
#pragma unroll
    for (int mt = 0; mt < 4; mt++) {
#pragma unroll
        for (int nt = 0; nt < 4; nt++) {
#pragma unroll
            for (int eh = 0; eh < 2; eh++) {
                int m = m0 + wm * 64 + mt * 16 + quad + eh * 8;
                int n = n0 + wn * 32 + nt * 8 + qt;
                float v0 = acc[mt][nt][eh * 2 + 0] + bias[n];
                float v1 = acc[mt][nt][eh * 2 + 1] + bias[n + 1];
                if (EPI == 0) {
                    v0 = fmaxf(v0, 0.f); v1 = fmaxf(v1, 0.f);
                    size_t o = (size_t)m * Nn + n;
                    __half h0, l0, h1, l1;
                    split_h(v0, h0, l0); split_h(v1, h1, l1);
                    *(__half2*)(Oh + o) = __halves2half2(h0, h1);
                    *(__half2*)(Ol + o) = __halves2half2(l0, l1);
                } else if (EPI == 1) {
#pragma unroll
                    for (int e = 0; e < 2; e++) {
                        float v = (e == 0) ? v0 : v1;
                        int nn = n + e;
                        size_t si = (size_t)m * Nn + nn;
                        v += __half2float(Sh[si]) + __half2float(Sl[si]);
                        int bb = m >> 10;            // m = b*F + f
                        int f  = m & (F_ - 1);
                        int np = invp[si];
                        size_t o = ((size_t)(bb * N_ + np)) * F_ + f;
                        __half h, l; split_h(v, h, l);
                        Oh[o] = h; Ol[o] = l;
                    }
                } else {  // EPI == 3
                    *(float2*)(Of + (size_t)m * Nn + n) = make_float2(v0, v1);
                }
            }
        }
    }
}

// ---------------------------------------------------------------------------
// Launch
// ---------------------------------------------------------------------------
extern "C" void kernel_launch(void* const* d_in, const int* in_sizes, int n_in,
                              void* d_out, int out_size) {
    const float* x   = (const float*)d_in[0];
    const float* sw1 = (const float*)d_in[1];
    const float* sb1 = (const float*)d_in[2];
    const float* sw2 = (const float*)d_in[3];
    const float* sb2 = (const float*)d_in[4];
    const float* fw1 = (const float*)d_in[5];
    const float* fb1 = (const float*)d_in[6];
    const float* fw2 = (const float*)d_in[7];
    const float* fb2 = (const float*)d_in[8];
    float* out = (float*)d_out;

    void *p_xs_hi, *p_xs_lo, *p_invp, *p_h_hi, *p_h_lo, *p_y2_hi, *p_y2_lo,
         *p_h2_hi, *p_h2_lo, *p_sw1, *p_sw2, *p_fw1, *p_fw2;
    cudaGetSymbolAddress(&p_xs_hi, g_xs_hi);
    cudaGetSymbolAddress(&p_xs_lo, g_xs_lo);
    cudaGetSymbolAddress(&p_invp,  g_invp);
    cudaGetSymbolAddress(&p_h_hi,  g_h_hi);
    cudaGetSymbolAddress(&p_h_lo,  g_h_lo);
    cudaGetSymbolAddress(&p_y2_hi, g_y2_hi);
    cudaGetSymbolAddress(&p_y2_lo, g_y2_lo);
    cudaGetSymbolAddress(&p_h2_hi, g_h2_hi);
    cudaGetSymbolAddress(&p_h2_lo, g_h2_lo);
    cudaGetSymbolAddress(&p_sw1,   g_sw1);
    cudaGetSymbolAddress(&p_sw2,   g_sw2);
    cudaGetSymbolAddress(&p_fw1,   g_fw1);
    cudaGetSymbolAddress(&p_fw2,   g_fw2);

    cudaFuncSetAttribute(gemm_kernel<0>, cudaFuncAttributeMaxDynamicSharedMemorySize, SMEM_BYTES);
    cudaFuncSetAttribute(gemm_kernel<1>, cudaFuncAttributeMaxDynamicSharedMemorySize, SMEM_BYTES);
    cudaFuncSetAttribute(gemm_kernel<3>, cudaFuncAttributeMaxDynamicSharedMemorySize, SMEM_BYTES);

    round_kernel<<<(int)((SZ_SW1 + 255) / 256), 256>>>(sw1, (__half*)p_sw1, (int)SZ_SW1);
    round_kernel<<<(int)((SZ_SW2 + 255) / 256), 256>>>(sw2, (__half*)p_sw2, (int)SZ_SW2);
    round_kernel<<<(int)((SZ_FW1 + 255) / 256), 256>>>(fw1, (__half*)p_fw1, (int)SZ_FW1);
    round_kernel<<<(int)((SZ_FW2 + 255) / 256), 256>>>(fw2, (__half*)p_fw2, (int)SZ_FW2);

    sort_kernel<<<M1_, 512>>>(x, (__half*)p_xs_hi, (__half*)p_xs_lo,
                              (unsigned short*)p_invp);

    // G1: H = relu(Xs @ sw1^T + sb1)   [M1, HS]
    {
        dim3 g(HS_ / 128, M1_ / 128);
        gemm_kernel<0><<<g, 256, SMEM_BYTES>>>(
            M1_, HS_, N_,
            (__half*)p_xs_hi, (__half*)p_xs_lo, (__half*)p_sw1, sb1,
            (__half*)p_h_hi, (__half*)p_h_lo, nullptr,
            nullptr, nullptr, nullptr);
    }
    // G2: Y = H @ sw2^T + sb2 + Xs, unsort+transpose-scatter into Y2[B,N,F]
    {
        dim3 g(N_ / 128, M1_ / 128);
        gemm_kernel<1><<<g, 256, SMEM_BYTES>>>(
            M1_, N_, HS_,
            (__half*)p_h_hi, (__half*)p_h_lo, (__half*)p_sw2, sb2,
            (__half*)p_y2_hi, (__half*)p_y2_lo, nullptr,
            (__half*)p_xs_hi, (__half*)p_xs_lo,
            (const unsigned short*)p_invp);
    }
    // G3: H2 = relu(Y2 @ fw1^T + fb1)  [M2, HF]
    {
        dim3 g(HF_ / 128, M2_ / 128);
        gemm_kernel<0><<<g, 256, SMEM_BYTES>>>(
            M2_, HF_, F_,
            (__half*)p_y2_hi, (__half*)p_y2_lo, (__half*)p_fw1, fb1,
            (__half*)p_h2_hi, (__half*)p_h2_lo, nullptr,
            nullptr, nullptr, nullptr);
    }
    // G4: out = H2 @ fw2^T + fb2       [M2, OUT] fp32
    {
        dim3 g(OUT_ / 128, M2_ / 128);
        gemm_kernel<3><<<g, 256, SMEM_BYTES>>>(
            M2_, OUT_, HF_,
            (__half*)p_h2_hi, (__half*)p_h2_lo, (__half*)p_fw2, fb2,
            nullptr, nullptr, out,
            nullptr, nullptr, nullptr);
    }
}

// round 13
// speedup vs baseline: 2.4945x; 1.5697x over previous
#include <cuda_runtime.h>
#include <cuda_fp16.h>
#include <cstdint>

// ---------------------------------------------------------------------------
// Problem dims
// ---------------------------------------------------------------------------
#define B_   32
#define N_   2048
#define F_   1024
#define HS_  8192
#define HF_  4096
#define M1_  (B_ * F_)   // 32768
#define M2_  (B_ * N_)   // 65536
#define OUT_ 1024

// ---------------------------------------------------------------------------
// Device-global scratch
// ---------------------------------------------------------------------------
constexpr size_t SZ_XS  = (size_t)M1_ * N_;
constexpr size_t SZ_H   = (size_t)M1_ * HS_;
constexpr size_t SZ_Y2  = (size_t)M2_ * F_;
constexpr size_t SZ_H2  = (size_t)M2_ * HF_;
constexpr size_t SZ_SW1 = (size_t)HS_ * N_;
constexpr size_t SZ_SW2 = (size_t)N_ * HS_;
constexpr size_t SZ_FW1 = (size_t)HF_ * F_;
constexpr size_t SZ_FW2 = (size_t)OUT_ * HF_;

__device__ __half g_xs[SZ_XS];          // single fp16 activation (GEMM A)
__device__ __half g_xs_lo[SZ_XS];       // lo limb kept ONLY for skip-add precision
__device__ unsigned short g_invp[SZ_XS];
__device__ __half g_h[SZ_H];
__device__ __half g_y2[SZ_Y2];
__device__ __half g_h2[SZ_H2];
__device__ __half g_sw1[SZ_SW1];
__device__ __half g_sw2[SZ_SW2];
__device__ __half g_fw1[SZ_FW1];
__device__ __half g_fw2[SZ_FW2];

// ---------------------------------------------------------------------------
// Helpers
// ---------------------------------------------------------------------------
__device__ __forceinline__ void split_h(float v, __half& h, __half& l) {
    h = __float2half_rn(v);
    l = __float2half_rn(v - __half2float(h));
}

__global__ __launch_bounds__(256) void round_kernel(const float* __restrict__ in,
                             __half* __restrict__ w, int n) {
    int i = blockIdx.x * 256 + threadIdx.x;
    if (i < n) w[i] = __float2half_rn(in[i]);
}

// ---------------------------------------------------------------------------
// Sort kernel (validated core; emits fp16 xs + lo limb for the skip path)
// ---------------------------------------------------------------------------
__global__ __launch_bounds__(512) void sort_kernel(
    const float* __restrict__ x,
    __half* __restrict__ xs, __half* __restrict__ xs_lo,
    unsigned short* __restrict__ invp)
{
    __shared__ unsigned long long keys[N_];
    __shared__ float xorig[N_];
    __shared__ float xsv[N_];
    __shared__ unsigned short invs[N_];

    const int m = blockIdx.x;
    const int b = m >> 10;
    const int f = m & (F_ - 1);
    const float* xrow = x + ((size_t)b * N_) * F_ + f;

    for (int j = threadIdx.x; j < N_; j += 512) {
        float v = xrow[(size_t)j * F_];
        unsigned u = __float_as_uint(v);
        u = (u & 0x80000000u) ? ~u : (u | 0x80000000u);
        keys[j] = ((unsigned long long)u << 16) | (unsigned)j;
        xorig[j] = v;
    }
    __syncthreads();

    for (int k = 2; k <= N_; k <<= 1) {
        for (int j = k >> 1; j > 0; j >>= 1) {
            for (int t = threadIdx.x; t < N_ / 2; t += 512) {
                int i = ((t & ~(j - 1)) << 1) | (t & (j - 1));
                int l = i | j;
                bool up = ((i & k) == 0);
                unsigned long long a = keys[i], c = keys[l];
                if ((a > c) == up) { keys[i] = c; keys[l] = a; }
            }
            __syncthreads();
        }
    }

    for (int jslot = threadIdx.x; jslot < N_; jslot += 512) {
        int pj = (int)(keys[jslot] & 0xFFFFu);
        xsv[pj] = xorig[jslot];
        invs[pj] = (unsigned short)jslot;
    }
    __syncthreads();

    size_t base = (size_t)m * N_;
    for (int i = threadIdx.x; i < N_; i += 512) {
        __half h, l;
        split_h(xsv[i], h, l);
        xs[base + i] = h;
        xs_lo[base + i] = l;
        invp[base + i] = invs[i];
    }
}

// ---------------------------------------------------------------------------
// GEMM: C[M,N] = A[M,K] @ W[N,K]^T, single fp16 A and W, fp32 accum mma.sync.
// 128x128 tile, BK=32, 6-stage cp.async (prefetch depth 5), swizzled 64B rows,
// 2 CTAs/SM, 1 barrier per K-tile.
// ---------------------------------------------------------------------------
__device__ __forceinline__ void cp16(unsigned s, const void* g) {
    asm volatile("cp.async.cg.shared.global [%0], [%1], 16;\n" :: "r"(s), "l"(g) : "memory");
}
__device__ __forceinline__ void cp_commit() {
    asm volatile("cp.async.commit_group;\n" ::: "memory");
}
template <int Np>
__device__ __forceinline__ void cp_waitg() {
    asm volatile("cp.async.wait_group %0;\n" :: "n"(Np) : "memory");
}
__device__ __forceinline__ void ldsm4(unsigned* r, unsigned addr) {
    asm volatile("ldmatrix.sync.aligned.m8n8.x4.shared.b16 {%0,%1,%2,%3}, [%4];\n"
        : "=r"(r[0]), "=r"(r[1]), "=r"(r[2]), "=r"(r[3]) : "r"(addr));
}
__device__ __forceinline__ void ldsm2(unsigned* r, unsigned addr) {
    asm volatile("ldmatrix.sync.aligned.m8n8.x2.shared.b16 {%0,%1}, [%2];\n"
        : "=r"(r[0]), "=r"(r[1]) : "r"(addr));
}
__device__ __forceinline__ void mma_f16(float* c, const unsigned* a, const unsigned* b) {
    asm volatile(
        "mma.sync.aligned.m16n8k16.row.col.f32.f16.f16.f32 "
        "{%0,%1,%2,%3}, {%4,%5,%6,%7}, {%8,%9}, {%0,%1,%2,%3};\n"
        : "+f"(c[0]), "+f"(c[1]), "+f"(c[2]), "+f"(c[3])
        : "r"(a[0]), "r"(a[1]), "r"(a[2]), "r"(a[3]), "r"(b[0]), "r"(b[1]));
}

// stage: A 8KB | W 8KB, rows of 64B, XOR-swizzled 16B chunks
#define SS_      16384
#define A_OFF    0
#define W_OFF    8192
#define NSTAGE   6
#define PREF     5
#define SMEM_BYTES (NSTAGE * SS_)   // 98304

__device__ __forceinline__ unsigned sw_off(int row, int clog) {
    return (unsigned)(row * 64 + ((clog ^ (row & 3)) << 4));
}

__device__ __forceinline__ void stage_load(
    unsigned sst,
    const __half* __restrict__ A, const __half* __restrict__ W,
    int m0, int n0, int K, int k0, int tid)
{
#pragma unroll
    for (int it = 0; it < 4; it++) {       // 1024 chunks / 256 threads
        int c = tid + it * 256;
        int arr = c >> 9;                  // 0:A 1:W
        int cc = c & 511;
        int row = cc >> 2, clog = cc & 3;
        unsigned dst = sst + arr * 8192 + sw_off(row, clog);
        const __half* base = arr ? W : A;
        int r0 = arr ? n0 : m0;
        cp16(dst, base + (size_t)(r0 + row) * K + k0 + clog * 8);
    }
}

// EPI: 0 = bias+relu -> fp16; 1 = bias+skip(hi+lo)+unsort-scatter -> fp16;
//      3 = bias -> fp32
template <int EPI>
__global__ __launch_bounds__(256, 2) void gemm_kernel(
    int M, int Nn, int K,
    const __half* __restrict__ A, const __half* __restrict__ W,
    const float* __restrict__ bias,
    __half* __restrict__ Oh, float* __restrict__ Of,
    const __half* __restrict__ Sh, const __half* __restrict__ Sl,
    const unsigned short* __restrict__ invp)
{
    extern __shared__ __half smem[];
    const int tid = threadIdx.x;
    const int m0 = blockIdx.y * 128;
    const int n0 = blockIdx.x * 128;
    const unsigned sbase = (unsigned)__cvta_generic_to_shared(smem);

    float acc[4][4][4];
#pragma unroll
    for (int a = 0; a < 4; a++)
#pragma unroll
        for (int b = 0; b < 4; b++)
#pragma unroll
            for (int e = 0; e < 4; e++) acc[a][b][e] = 0.f;

    const int nk = K >> 5;
    const int lane = tid & 31;
    const int wid = tid >> 5;
    const int wm = wid >> 2;   // 0..1 -> 64 rows
    const int wn = wid & 3;    // 0..3 -> 32 cols

    // prologue: PREF stages in flight
#pragma unroll
    for (int s = 0; s < PREF; s++) {
        stage_load(sbase + s * SS_, A, W, m0, n0, K, s * 32, tid);
        cp_commit();
    }

    for (int kt = 0; kt < nk; kt++) {
        cp_waitg<PREF - 1>();   // stage kt landed (this thread's chunks)
        __syncthreads();        // publish; fences reuse of recycled buffer

        const unsigned sst = sbase + (kt % NSTAGE) * SS_;
#pragma unroll
        for (int step = 0; step < 2; step++) {
            unsigned a_r[4][4];
            const int arow = lane & 15;
            const int ag = step * 2 + (lane >> 4);
#pragma unroll
            for (int mt = 0; mt < 4; mt++) {
                int row = wm * 64 + mt * 16 + arow;
                ldsm4(a_r[mt], sst + A_OFF + sw_off(row, ag));
            }
            const int brow = wn * 32 + (lane & 7);
            const int bg = step * 2 + ((lane >> 3) & 1);
#pragma unroll
            for (int nt = 0; nt < 4; nt++) {
                int row = brow + nt * 8;
                unsigned bw[2];
                ldsm2(bw, sst + W_OFF + sw_off(row, bg));
#pragma unroll
                for (int mt = 0; mt < 4; mt++) mma_f16(acc[mt][nt], a_r[mt], bw);
            }
        }

        if (kt + PREF < nk)
            stage_load(sbase + ((kt + PREF) % NSTAGE) * SS_, A, W,
                       m0, n0, K, (kt + PREF) * 32, tid);
        cp_commit();            // keep group count uniform
    }

    // ---------------- epilogue ----------------
    const int quad = lane >> 2;
    const int qt = (lane & 3) << 1;
#pragma unroll
    for (int mt = 0; mt < 4; mt++) {
#pragma unroll
        for (int nt = 0; nt < 4; nt++) {
#pragma unroll
            for (int eh = 0; eh < 2; eh++) {
                int m = m0 + wm * 64 + mt * 16 + quad + eh * 8;
                int n = n0 + wn * 32 + nt * 8 + qt;
                float v0 = acc[mt][nt][eh * 2 + 0] + bias[n];
                float v1 = acc[mt][nt][eh * 2 + 1] + bias[n + 1];
                if (EPI == 0) {
                    v0 = fmaxf(v0, 0.f); v1 = fmaxf(v1, 0.f);
                    size_t o = (size_t)m * Nn + n;
                    *(__half2*)(Oh + o) =
                        __halves2half2(__float2half_rn(v0), __float2half_rn(v1));
                } else if (EPI == 1) {
#pragma unroll
                    for (int e = 0; e < 2; e++) {
                        float v = (e == 0) ? v0 : v1;
                        int nn = n + e;
                        size_t si = (size_t)m * Nn + nn;
                        v += __half2float(Sh[si]) + __half2float(Sl[si]);
                        int bb = m >> 10;            // m = b*F + f
                        int f  = m & (F_ - 1);
                        int np = invp[si];
                        size_t o = ((size_t)(bb * N_ + np)) * F_ + f;
                        Oh[o] = __float2half_rn(v);
                    }
                } else {  // EPI == 3
                    *(float2*)(Of + (size_t)m * Nn + n) = make_float2(v0, v1);
                }
            }
        }
    }
}

// ---------------------------------------------------------------------------
// Launch
// ---------------------------------------------------------------------------
extern "C" void kernel_launch(void* const* d_in, const int* in_sizes, int n_in,
                              void* d_out, int out_size) {
    const float* x   = (const float*)d_in[0];
    const float* sw1 = (const float*)d_in[1];
    const float* sb1 = (const float*)d_in[2];
    const float* sw2 = (const float*)d_in[3];
    const float* sb2 = (const float*)d_in[4];
    const float* fw1 = (const float*)d_in[5];
    const float* fb1 = (const float*)d_in[6];
    const float* fw2 = (const float*)d_in[7];
    const float* fb2 = (const float*)d_in[8];
    float* out = (float*)d_out;

    void *p_xs, *p_xs_lo, *p_invp, *p_h, *p_y2, *p_h2,
         *p_sw1, *p_sw2, *p_fw1, *p_fw2;
    cudaGetSymbolAddress(&p_xs,    g_xs);
    cudaGetSymbolAddress(&p_xs_lo, g_xs_lo);
    cudaGetSymbolAddress(&p_invp,  g_invp);
    cudaGetSymbolAddress(&p_h,     g_h);
    cudaGetSymbolAddress(&p_y2,    g_y2);
    cudaGetSymbolAddress(&p_h2,    g_h2);
    cudaGetSymbolAddress(&p_sw1,   g_sw1);
    cudaGetSymbolAddress(&p_sw2,   g_sw2);
    cudaGetSymbolAddress(&p_fw1,   g_fw1);
    cudaGetSymbolAddress(&p_fw2,   g_fw2);

    cudaFuncSetAttribute(gemm_kernel<0>, cudaFuncAttributeMaxDynamicSharedMemorySize, SMEM_BYTES);
    cudaFuncSetAttribute(gemm_kernel<1>, cudaFuncAttributeMaxDynamicSharedMemorySize, SMEM_BYTES);
    cudaFuncSetAttribute(gemm_kernel<3>, cudaFuncAttributeMaxDynamicSharedMemorySize, SMEM_BYTES);

    round_kernel<<<(int)((SZ_SW1 + 255) / 256), 256>>>(sw1, (__half*)p_sw1, (int)SZ_SW1);
    round_kernel<<<(int)((SZ_SW2 + 255) / 256), 256>>>(sw2, (__half*)p_sw2, (int)SZ_SW2);
    round_kernel<<<(int)((SZ_FW1 + 255) / 256), 256>>>(fw1, (__half*)p_fw1, (int)SZ_FW1);
    round_kernel<<<(int)((SZ_FW2 + 255) / 256), 256>>>(fw2, (__half*)p_fw2, (int)SZ_FW2);

    sort_kernel<<<M1_, 512>>>(x, (__half*)p_xs, (__half*)p_xs_lo,
                              (unsigned short*)p_invp);

    // G1: H = relu(Xs @ sw1^T + sb1)   [M1, HS]
    {
        dim3 g(HS_ / 128, M1_ / 128);
        gemm_kernel<0><<<g, 256, SMEM_BYTES>>>(
            M1_, HS_, N_,
            (__half*)p_xs, (__half*)p_sw1, sb1,
            (__half*)p_h, nullptr,
            nullptr, nullptr, nullptr);
    }
    // G2: Y = H @ sw2^T + sb2 + Xs(hi+lo), unsort+transpose-scatter -> Y2[B,N,F]
    {
        dim3 g(N_ / 128, M1_ / 128);
        gemm_kernel<1><<<g, 256, SMEM_BYTES>>>(
            M1_, N_, HS_,
            (__half*)p_h, (__half*)p_sw2, sb2,
            (__half*)p_y2, nullptr,
            (__half*)p_xs, (__half*)p_xs_lo,
            (const unsigned short*)p_invp);
    }
    // G3: H2 = relu(Y2 @ fw1^T + fb1)  [M2, HF]
    {
        dim3 g(HF_ / 128, M2_ / 128);
        gemm_kernel<0><<<g, 256, SMEM_BYTES>>>(
            M2_, HF_, F_,
            (__half*)p_y2, (__half*)p_fw1, fb1,
            (__half*)p_h2, nullptr,
            nullptr, nullptr, nullptr);
    }
    // G4: out = H2 @ fw2^T + fb2       [M2, OUT] fp32
    {
        dim3 g(OUT_ / 128, M2_ / 128);
        gemm_kernel<3><<<g, 256, SMEM_BYTES>>>(
            M2_, OUT_, HF_,
            (__half*)p_h2, (__half*)p_fw2, fb2,
            nullptr, out,
            nullptr, nullptr, nullptr);
    }
}

// round 14
// speedup vs baseline: 2.9807x; 1.1949x over previous
#include <cuda_runtime.h>
#include <cuda_fp16.h>
#include <cstdint>

// ---------------------------------------------------------------------------
// Problem dims
// ---------------------------------------------------------------------------
#define B_   32
#define N_   2048
#define F_   1024
#define HS_  8192
#define HF_  4096
#define M1_  (B_ * F_)   // 32768
#define M2_  (B_ * N_)   // 65536
#define OUT_ 1024

// ---------------------------------------------------------------------------
// Device-global scratch
// ---------------------------------------------------------------------------
constexpr size_t SZ_XS  = (size_t)M1_ * N_;
constexpr size_t SZ_H   = (size_t)M1_ * HS_;
constexpr size_t SZ_Y2  = (size_t)M2_ * F_;
constexpr size_t SZ_H2  = (size_t)M2_ * HF_;
constexpr size_t SZ_SW1 = (size_t)HS_ * N_;
constexpr size_t SZ_SW2 = (size_t)N_ * HS_;
constexpr size_t SZ_FW1 = (size_t)HF_ * F_;
constexpr size_t SZ_FW2 = (size_t)OUT_ * HF_;

__device__ __half g_xs[SZ_XS];          // single fp16 activation (GEMM A)
__device__ __half g_xs_lo[SZ_XS];       // lo limb kept ONLY for skip-add precision
__device__ unsigned short g_invp[SZ_XS];
__device__ __half g_h[SZ_H];
__device__ __half g_y2[SZ_Y2];
__device__ __half g_h2[SZ_H2];
__device__ __half g_sw1[SZ_SW1];
__device__ __half g_sw2[SZ_SW2];
__device__ __half g_fw1[SZ_FW1];
__device__ __half g_fw2[SZ_FW2];

// ---------------------------------------------------------------------------
// Helpers
// ---------------------------------------------------------------------------
__device__ __forceinline__ void split_h(float v, __half& h, __half& l) {
    h = __float2half_rn(v);
    l = __float2half_rn(v - __half2float(h));
}

__global__ __launch_bounds__(256) void round_kernel(const float* __restrict__ in,
                             __half* __restrict__ w, int n) {
    int i = blockIdx.x * 256 + threadIdx.x;
    if (i < n) w[i] = __float2half_rn(in[i]);
}

// ---------------------------------------------------------------------------
// Sort kernel (validated core; emits fp16 xs + lo limb for the skip path)
// ---------------------------------------------------------------------------
__global__ __launch_bounds__(512) void sort_kernel(
    const float* __restrict__ x,
    __half* __restrict__ xs, __half* __restrict__ xs_lo,
    unsigned short* __restrict__ invp)
{
    __shared__ unsigned long long keys[N_];
    __shared__ float xorig[N_];
    __shared__ float xsv[N_];
    __shared__ unsigned short invs[N_];

    const int m = blockIdx.x;
    const int b = m >> 10;
    const int f = m & (F_ - 1);
    const float* xrow = x + ((size_t)b * N_) * F_ + f;

    for (int j = threadIdx.x; j < N_; j += 512) {
        float v = xrow[(size_t)j * F_];
        unsigned u = __float_as_uint(v);
        u = (u & 0x80000000u) ? ~u : (u | 0x80000000u);
        keys[j] = ((unsigned long long)u << 16) | (unsigned)j;
        xorig[j] = v;
    }
    __syncthreads();

    for (int k = 2; k <= N_; k <<= 1) {
        for (int j = k >> 1; j > 0; j >>= 1) {
            for (int t = threadIdx.x; t < N_ / 2; t += 512) {
                int i = ((t & ~(j - 1)) << 1) | (t & (j - 1));
                int l = i | j;
                bool up = ((i & k) == 0);
                unsigned long long a = keys[i], c = keys[l];
                if ((a > c) == up) { keys[i] = c; keys[l] = a; }
            }
            __syncthreads();
        }
    }

    for (int jslot = threadIdx.x; jslot < N_; jslot += 512) {
        int pj = (int)(keys[jslot] & 0xFFFFu);
        xsv[pj] = xorig[jslot];
        invs[pj] = (unsigned short)jslot;
    }
    __syncthreads();

    size_t base = (size_t)m * N_;
    for (int i = threadIdx.x; i < N_; i += 512) {
        __half h, l;
        split_h(xsv[i], h, l);
        xs[base + i] = h;
        xs_lo[base + i] = l;
        invp[base + i] = invs[i];
    }
}

// ---------------------------------------------------------------------------
// GEMM: C[M,N] = A[M,K] @ W[N,K]^T, single fp16 A and W, fp32 accum mma.sync.
// 128x128 tile, BK=32, 6-stage cp.async (prefetch depth 5), swizzled 64B rows
// (conflict-free: chunk ^= (row>>1)&3), 2 CTAs/SM, 1 barrier per K-tile.
// ---------------------------------------------------------------------------
__device__ __forceinline__ void cp16(unsigned s, const void* g) {
    asm volatile("cp.async.cg.shared.global [%0], [%1], 16;\n" :: "r"(s), "l"(g) : "memory");
}
__device__ __forceinline__ void cp_commit() {
    asm volatile("cp.async.commit_group;\n" ::: "memory");
}
template <int Np>
__device__ __forceinline__ void cp_waitg() {
    asm volatile("cp.async.wait_group %0;\n" :: "n"(Np) : "memory");
}
__device__ __forceinline__ void ldsm4(unsigned* r, unsigned addr) {
    asm volatile("ldmatrix.sync.aligned.m8n8.x4.shared.b16 {%0,%1,%2,%3}, [%4];\n"
        : "=r"(r[0]), "=r"(r[1]), "=r"(r[2]), "=r"(r[3]) : "r"(addr));
}
__device__ __forceinline__ void ldsm2(unsigned* r, unsigned addr) {
    asm volatile("ldmatrix.sync.aligned.m8n8.x2.shared.b16 {%0,%1}, [%2];\n"
        : "=r"(r[0]), "=r"(r[1]) : "r"(addr));
}
__device__ __forceinline__ void mma_f16(float* c, const unsigned* a, const unsigned* b) {
    asm volatile(
        "mma.sync.aligned.m16n8k16.row.col.f32.f16.f16.f32 "
        "{%0,%1,%2,%3}, {%4,%5,%6,%7}, {%8,%9}, {%0,%1,%2,%3};\n"
        : "+f"(c[0]), "+f"(c[1]), "+f"(c[2]), "+f"(c[3])
        : "r"(a[0]), "r"(a[1]), "r"(a[2]), "r"(a[3]), "r"(b[0]), "r"(b[1]));
}

// stage: A 8KB | W 8KB, rows of 64B, XOR-swizzled 16B chunks
#define SS_      16384
#define A_OFF    0
#define W_OFF    8192
#define NSTAGE   6
#define PREF     5
#define SMEM_BYTES (NSTAGE * SS_)   // 98304

// Conflict-free swizzle: within any 8-consecutive-row ldmatrix phase, the four
// rows sharing a 64B half (r, r+2, r+4, r+6) get 4 distinct 16B chunks.
__device__ __forceinline__ unsigned sw_off(int row, int clog) {
    return (unsigned)(row * 64 + ((clog ^ ((row >> 1) & 3)) << 4));
}

__device__ __forceinline__ void stage_load(
    unsigned sst,
    const __half* __restrict__ A, const __half* __restrict__ W,
    int m0, int n0, int K, int k0, int tid)
{
#pragma unroll
    for (int it = 0; it < 4; it++) {       // 1024 chunks / 256 threads
        int c = tid + it * 256;
        int arr = c >> 9;                  // 0:A 1:W
        int cc = c & 511;
        int row = cc >> 2, clog = cc & 3;
        unsigned dst = sst + arr * 8192 + sw_off(row, clog);
        const __half* base = arr ? W : A;
        int r0 = arr ? n0 : m0;
        cp16(dst, base + (size_t)(r0 + row) * K + k0 + clog * 8);
    }
}

// EPI: 0 = bias+relu -> fp16; 1 = bias+skip(hi+lo)+unsort-scatter -> fp16;
//      3 = bias -> fp32
template <int EPI>
__global__ __launch_bounds__(256, 2) void gemm_kernel(
    int M, int Nn, int K,
    const __half* __restrict__ A, const __half* __restrict__ W,
    const float* __restrict__ bias,
    __half* __restrict__ Oh, float* __restrict__ Of,
    const __half* __restrict__ Sh, const __half* __restrict__ Sl,
    const unsigned short* __restrict__ invp)
{
    extern __shared__ __half smem[];
    const int tid = threadIdx.x;
    const int m0 = blockIdx.y * 128;
    const int n0 = blockIdx.x * 128;
    const unsigned sbase = (unsigned)__cvta_generic_to_shared(smem);

    float acc[4][4][4];
#pragma unroll
    for (int a = 0; a < 4; a++)
#pragma unroll
        for (int b = 0; b < 4; b++)
#pragma unroll
            for (int e = 0; e < 4; e++) acc[a][b][e] = 0.f;

    const int nk = K >> 5;
    const int lane = tid & 31;
    const int wid = tid >> 5;
    const int wm = wid >> 2;   // 0..1 -> 64 rows
    const int wn = wid & 3;    // 0..3 -> 32 cols

    // prologue: PREF stages in flight
#pragma unroll
    for (int s = 0; s < PREF; s++) {
        stage_load(sbase + s * SS_, A, W, m0, n0, K, s * 32, tid);
        cp_commit();
    }

    for (int kt = 0; kt < nk; kt++) {
        cp_waitg<PREF - 1>();   // stage kt landed (this thread's chunks)
        __syncthreads();        // publish; fences reuse of recycled buffer

        const unsigned sst = sbase + (kt % NSTAGE) * SS_;
#pragma unroll
        for (int step = 0; step < 2; step++) {
            unsigned a_r[4][4];
            const int arow = lane & 15;
            const int ag = step * 2 + (lane >> 4);
#pragma unroll
            for (int mt = 0; mt < 4; mt++) {
                int row = wm * 64 + mt * 16 + arow;
                ldsm4(a_r[mt], sst + A_OFF + sw_off(row, ag));
            }
            const int brow = wn * 32 + (lane & 7);
            const int bg = step * 2 + ((lane >> 3) & 1);
#pragma unroll
            for (int nt = 0; nt < 4; nt++) {
                int row = brow + nt * 8;
                unsigned bw[2];
                ldsm2(bw, sst + W_OFF + sw_off(row, bg));
#pragma unroll
                for (int mt = 0; mt < 4; mt++) mma_f16(acc[mt][nt], a_r[mt], bw);
            }
        }

        if (kt + PREF < nk)
            stage_load(sbase + ((kt + PREF) % NSTAGE) * SS_, A, W,
                       m0, n0, K, (kt + PREF) * 32, tid);
        cp_commit();            // keep group count uniform
    }

    // ---------------- epilogue ----------------
    const int quad = lane >> 2;
    const int qt = (lane & 3) << 1;
#pragma unroll
    for (int mt = 0; mt < 4; mt++) {
#pragma unroll
        for (int nt = 0; nt < 4; nt++) {
#pragma unroll
            for (int eh = 0; eh < 2; eh++) {
                int m = m0 + wm * 64 + mt * 16 + quad + eh * 8;
                int n = n0 + wn * 32 + nt * 8 + qt;
                float v0 = acc[mt][nt][eh * 2 + 0] + bias[n];
                float v1 = acc[mt][nt][eh * 2 + 1] + bias[n + 1];
                if (EPI == 0) {
                    v0 = fmaxf(v0, 0.f); v1 = fmaxf(v1, 0.f);
                    size_t o = (size_t)m * Nn + n;
                    *(__half2*)(Oh + o) =
                        __halves2half2(__float2half_rn(v0), __float2half_rn(v1));
                } else if (EPI == 1) {
#pragma unroll
                    for (int e = 0; e < 2; e++) {
                        float v = (e == 0) ? v0 : v1;
                        int nn = n + e;
                        size_t si = (size_t)m * Nn + nn;
                        v += __half2float(Sh[si]) + __half2float(Sl[si]);
                        int bb = m >> 10;            // m = b*F + f
                        int f  = m & (F_ - 1);
                        int np = invp[si];
                        size_t o = ((size_t)(bb * N_ + np)) * F_ + f;
                        Oh[o] = __float2half_rn(v);
                    }
                } else {  // EPI == 3
                    *(float2*)(Of + (size_t)m * Nn + n) = make_float2(v0, v1);
                }
            }
        }
    }
}

// ---------------------------------------------------------------------------
// Launch
// ---------------------------------------------------------------------------
extern "C" void kernel_launch(void* const* d_in, const int* in_sizes, int n_in,
                              void* d_out, int out_size) {
    const float* x   = (const float*)d_in[0];
    const float* sw1 = (const float*)d_in[1];
    const float* sb1 = (const float*)d_in[2];
    const float* sw2 = (const float*)d_in[3];
    const float* sb2 = (const float*)d_in[4];
    const float* fw1 = (const float*)d_in[5];
    const float* fb1 = (const float*)d_in[6];
    const float* fw2 = (const float*)d_in[7];
    const float* fb2 = (const float*)d_in[8];
    float* out = (float*)d_out;

    void *p_xs, *p_xs_lo, *p_invp, *p_h, *p_y2, *p_h2,
         *p_sw1, *p_sw2, *p_fw1, *p_fw2;
    cudaGetSymbolAddress(&p_xs,    g_xs);
    cudaGetSymbolAddress(&p_xs_lo, g_xs_lo);
    cudaGetSymbolAddress(&p_invp,  g_invp);
    cudaGetSymbolAddress(&p_h,     g_h);
    cudaGetSymbolAddress(&p_y2,    g_y2);
    cudaGetSymbolAddress(&p_h2,    g_h2);
    cudaGetSymbolAddress(&p_sw1,   g_sw1);
    cudaGetSymbolAddress(&p_sw2,   g_sw2);
    cudaGetSymbolAddress(&p_fw1,   g_fw1);
    cudaGetSymbolAddress(&p_fw2,   g_fw2);

    cudaFuncSetAttribute(gemm_kernel<0>, cudaFuncAttributeMaxDynamicSharedMemorySize, SMEM_BYTES);
    cudaFuncSetAttribute(gemm_kernel<1>, cudaFuncAttributeMaxDynamicSharedMemorySize, SMEM_BYTES);
    cudaFuncSetAttribute(gemm_kernel<3>, cudaFuncAttributeMaxDynamicSharedMemorySize, SMEM_BYTES);

    round_kernel<<<(int)((SZ_SW1 + 255) / 256), 256>>>(sw1, (__half*)p_sw1, (int)SZ_SW1);
    round_kernel<<<(int)((SZ_SW2 + 255) / 256), 256>>>(sw2, (__half*)p_sw2, (int)SZ_SW2);
    round_kernel<<<(int)((SZ_FW1 + 255) / 256), 256>>>(fw1, (__half*)p_fw1, (int)SZ_FW1);
    round_kernel<<<(int)((SZ_FW2 + 255) / 256), 256>>>(fw2, (__half*)p_fw2, (int)SZ_FW2);

    sort_kernel<<<M1_, 512>>>(x, (__half*)p_xs, (__half*)p_xs_lo,
                              (unsigned short*)p_invp);

    // G1: H = relu(Xs @ sw1^T + sb1)   [M1, HS]
    {
        dim3 g(HS_ / 128, M1_ / 128);
        gemm_kernel<0><<<g, 256, SMEM_BYTES>>>(
            M1_, HS_, N_,
            (__half*)p_xs, (__half*)p_sw1, sb1,
            (__half*)p_h, nullptr,
            nullptr, nullptr, nullptr);
    }
    // G2: Y = H @ sw2^T + sb2 + Xs(hi+lo), unsort+transpose-scatter -> Y2[B,N,F]
    {
        dim3 g(N_ / 128, M1_ / 128);
        gemm_kernel<1><<<g, 256, SMEM_BYTES>>>(
            M1_, N_, HS_,
            (__half*)p_h, (__half*)p_sw2, sb2,
            (__half*)p_y2, nullptr,
            (__half*)p_xs, (__half*)p_xs_lo,
            (const unsigned short*)p_invp);
    }
    // G3: H2 = relu(Y2 @ fw1^T + fb1)  [M2, HF]
    {
        dim3 g(HF_ / 128, M2_ / 128);
        gemm_kernel<0><<<g, 256, SMEM_BYTES>>>(
            M2_, HF_, F_,
            (__half*)p_y2, (__half*)p_fw1, fb1,
            (__half*)p_h2, nullptr,
            nullptr, nullptr, nullptr);
    }
    // G4: out = H2 @ fw2^T + fb2       [M2, OUT] fp32
    {
        dim3 g(OUT_ / 128, M2_ / 128);
        gemm_kernel<3><<<g, 256, SMEM_BYTES>>>(
            M2_, OUT_, HF_,
            (__half*)p_h2, (__half*)p_fw2, fb2,
            nullptr, out,
            nullptr, nullptr, nullptr);
    }
}